// round 1
// baseline (speedup 1.0000x reference)
#include <cuda_runtime.h>
#include <math.h>

#define IMG_H 800.0f
#define IMG_W 1280.0f
#define FSCALE (1.0f/16.0f)
#define PP 14
#define NUM_CLASSES 80
#define SCORE_TH 0.05f
#define NMS_TH 0.5f
#define MAX_DET 100
#define IOU_TH 0.5f
#define SCALE_CLAMP 4.135166556742356f
#define FH 50
#define FW 80
#define FC 1024
#define NIMG 2
#define NR 256
#define NGT 64

// Scratch (device globals; no allocation allowed)
__device__ float g_featvec[NIMG * NR * FC];
__device__ float g_boxes[NIMG * NR * 4];
__device__ float g_scores[NIMG * NR];

// ---------------------------------------------------------------------------
// Kernel 1: proposal<->gt matching. grid(2), block(256). One thread = proposal.
// iou_m[g,r]; per proposal r: max/first-argmax over g.
// ---------------------------------------------------------------------------
__global__ void match_kernel(const float* __restrict__ gt,
                             const float* __restrict__ prop,
                             float* __restrict__ out_idx,
                             float* __restrict__ out_lbl) {
    int n = blockIdx.x;
    int r = threadIdx.x;
    const float* p = prop + (n * NR + r) * 4;
    float px1 = p[0], py1 = p[1], px2 = p[2], py2 = p[3];
    float pa = (px2 - px1) * (py2 - py1);
    float best = -1.0f;
    int bi = 0;
    for (int g = 0; g < NGT; g++) {
        const float* gb = gt + (n * NGT + g) * 4;
        float gx1 = gb[0], gy1 = gb[1], gx2 = gb[2], gy2 = gb[3];
        float ga = (gx2 - gx1) * (gy2 - gy1);
        float lx = fmaxf(gx1, px1), ly = fmaxf(gy1, py1);
        float rx = fminf(gx2, px2), ry = fminf(gy2, py2);
        float w = fmaxf(rx - lx, 0.0f), h = fmaxf(ry - ly, 0.0f);
        float inter = w * h;
        float iou = inter / fmaxf(ga + pa - inter, 1e-9f);
        if (iou > best) { best = iou; bi = g; }
    }
    out_idx[n * NR + r] = (float)bi;
    out_lbl[n * NR + r] = (best >= IOU_TH) ? 1.0f : 0.0f;
}

// ---------------------------------------------------------------------------
// Kernel 2: ROIAlign (P=14, S=1) + average pool -> feat_vec.
// grid(256, 2) = (box, image), block(256). Thread t owns channels [4t, 4t+4)
// as one float4; loops the 196 sample points accumulating bilinear values.
// All 4 corner loads per point are coalesced LDG.128 across the block.
// ---------------------------------------------------------------------------
__global__ void roi_kernel(const float* __restrict__ feat,
                           const float* __restrict__ prop,
                           float* __restrict__ featvec) {
    int r = blockIdx.x;
    int n = blockIdx.y;
    int t = threadIdx.x;

    const float* p = prop + (n * NR + r) * 4;
    float x1 = p[0] * FSCALE, y1 = p[1] * FSCALE;
    float x2 = p[2] * FSCALE, y2 = p[3] * FSCALE;
    float bh = (y2 - y1) * (1.0f / (float)PP);
    float bw = (x2 - x1) * (1.0f / (float)PP);

    __shared__ int sy0[PP], sy1[PP], sx0[PP], sx1[PP];
    __shared__ float sly[PP], slx[PP];
    if (t < PP) {
        float gy = y1 + ((float)t + 0.5f) * bh - 0.5f;
        gy = fminf(fmaxf(gy, 0.0f), (float)(FH - 1));
        float y0 = floorf(gy);
        int y0i = (int)y0;
        sy0[t] = y0i;
        sy1[t] = min(y0i + 1, FH - 1);
        sly[t] = gy - y0;
    } else if (t < 2 * PP) {
        int i = t - PP;
        float gx = x1 + ((float)i + 0.5f) * bw - 0.5f;
        gx = fminf(fmaxf(gx, 0.0f), (float)(FW - 1));
        float x0 = floorf(gx);
        int x0i = (int)x0;
        sx0[i] = x0i;
        sx1[i] = min(x0i + 1, FW - 1);
        slx[i] = gx - x0;
    }
    __syncthreads();

    const float4* f = (const float4*)(feat + (size_t)n * FH * FW * FC);
    float4 acc = make_float4(0.f, 0.f, 0.f, 0.f);

    for (int py = 0; py < PP; py++) {
        int y0 = sy0[py], yb = sy1[py];
        float ly = sly[py], wy0 = 1.0f - ly;
        int rowA = y0 * FW;
        int rowB = yb * FW;
        for (int px = 0; px < PP; px++) {
            int x0 = sx0[px], xb = sx1[px];
            float lx = slx[px], wx0 = 1.0f - lx;
            float4 a = f[(size_t)(rowA + x0) * (FC / 4) + t];
            float4 b = f[(size_t)(rowA + xb) * (FC / 4) + t];
            float4 c = f[(size_t)(rowB + x0) * (FC / 4) + t];
            float4 d = f[(size_t)(rowB + xb) * (FC / 4) + t];
            float tx, bx;
            tx = a.x * wx0 + b.x * lx; bx = c.x * wx0 + d.x * lx;
            acc.x += wy0 * tx + ly * bx;
            tx = a.y * wx0 + b.y * lx; bx = c.y * wx0 + d.y * lx;
            acc.y += wy0 * tx + ly * bx;
            tx = a.z * wx0 + b.z * lx; bx = c.z * wx0 + d.z * lx;
            acc.z += wy0 * tx + ly * bx;
            tx = a.w * wx0 + b.w * lx; bx = c.w * wx0 + d.w * lx;
            acc.w += wy0 * tx + ly * bx;
        }
    }
    float inv = 1.0f / (float)(PP * PP);
    acc.x *= inv; acc.y *= inv; acc.z *= inv; acc.w *= inv;
    ((float4*)featvec)[(size_t)(n * NR + r) * (FC / 4) + t] = acc;
}

// ---------------------------------------------------------------------------
// Kernel 3: heads. grid(512) one block per proposal, block(128).
// Threads 0..80 compute cls logits (coalesced W_cls columns), threads 96..99
// compute box deltas. Thread 0 does softmax + decode.
// ---------------------------------------------------------------------------
__global__ void head_kernel(const float* __restrict__ featvec,
                            const float* __restrict__ prop,
                            const float* __restrict__ Wc,
                            const float* __restrict__ bc,
                            const float* __restrict__ Wb,
                            const float* __restrict__ bb,
                            float* __restrict__ boxes,
                            float* __restrict__ scores) {
    int gid = blockIdx.x;   // n*256 + r
    int t = threadIdx.x;
    __shared__ float sf[FC];
    __shared__ float slog[NUM_CLASSES + 1];
    __shared__ float sdel[4];

    const float* fv = featvec + (size_t)gid * FC;
    for (int i = t; i < FC; i += blockDim.x) sf[i] = fv[i];
    __syncthreads();

    if (t < NUM_CLASSES + 1) {
        float acc = bc[t];
        for (int k = 0; k < FC; k++) acc += sf[k] * Wc[k * (NUM_CLASSES + 1) + t];
        slog[t] = acc;
    } else if (t >= 96 && t < 100) {
        int c = t - 96;
        float acc = bb[c];
        for (int k = 0; k < FC; k++) acc += sf[k] * Wb[k * 4 + c];
        sdel[c] = acc;
    }
    __syncthreads();

    if (t == 0) {
        float m = -INFINITY;
        for (int c = 0; c <= NUM_CLASSES; c++) m = fmaxf(m, slog[c]);
        float s = 0.0f;
        float fg = -INFINITY;
        for (int c = 0; c <= NUM_CLASSES; c++) {
            float e = expf(slog[c] - m);
            s += e;
            if (c < NUM_CLASSES) fg = fmaxf(fg, e);
        }
        scores[gid] = fg / s;

        const float* p = prop + (size_t)gid * 4;
        float px1 = p[0], py1 = p[1], px2 = p[2], py2 = p[3];
        float wdt = px2 - px1, hgt = py2 - py1;
        float cx = px1 + 0.5f * wdt, cy = py1 + 0.5f * hgt;
        float dx = sdel[0] * 0.1f;
        float dy = sdel[1] * 0.1f;
        float dw = fminf(sdel[2] * 0.2f, SCALE_CLAMP);
        float dh = fminf(sdel[3] * 0.2f, SCALE_CLAMP);
        float pcx = dx * wdt + cx;
        float pcy = dy * hgt + cy;
        float pw = expf(dw) * wdt;
        float ph = expf(dh) * hgt;
        float ox1 = fminf(fmaxf(pcx - 0.5f * pw, 0.0f), IMG_W);
        float oy1 = fminf(fmaxf(pcy - 0.5f * ph, 0.0f), IMG_H);
        float ox2 = fminf(fmaxf(pcx + 0.5f * pw, 0.0f), IMG_W);
        float oy2 = fminf(fmaxf(pcy + 0.5f * ph, 0.0f), IMG_H);
        float* ob = boxes + (size_t)gid * 4;
        ob[0] = ox1; ob[1] = oy1; ob[2] = ox2; ob[3] = oy2;
    }
}

// ---------------------------------------------------------------------------
// Kernel 4: NMS + ranking + det write. grid(2) one block per image, block(256).
// Stable descending sort via O(R^2) rank count, 256x256 IoU bitmatrix in
// parallel, serial greedy over 8-word bitmasks (thread 0), then score
// threshold + stable rank<100, write det rows.
// ---------------------------------------------------------------------------
__global__ void nms_kernel(const float* __restrict__ boxes,
                           const float* __restrict__ scores,
                           float* __restrict__ det) {
    int n = blockIdx.x;
    int t = threadIdx.x;

    __shared__ float ss[NR];          // scores, original order
    __shared__ int order[NR];         // order[pos] = orig idx
    __shared__ float sb[NR][4];       // sorted boxes
    __shared__ unsigned int supmask[NR][8];
    __shared__ unsigned int keptw[8];
    __shared__ float smask[NR];

    float s_i = scores[n * NR + t];
    ss[t] = s_i;
    __syncthreads();

    // stable descending rank of this proposal
    int rk = 0;
    for (int j = 0; j < NR; j++) {
        float sj = ss[j];
        rk += (sj > s_i) || (sj == s_i && j < t);
    }
    order[rk] = t;
    __syncthreads();

    // gather sorted boxes
    {
        int oi = order[t];
        const float* bsrc = boxes + (size_t)(n * NR + oi) * 4;
        sb[t][0] = bsrc[0]; sb[t][1] = bsrc[1];
        sb[t][2] = bsrc[2]; sb[t][3] = bsrc[3];
    }
    if (t < 8) keptw[t] = 0u;
    __syncthreads();

    // IoU bitmatrix row t
    {
        float ax1 = sb[t][0], ay1 = sb[t][1], ax2 = sb[t][2], ay2 = sb[t][3];
        float aa = (ax2 - ax1) * (ay2 - ay1);
        for (int w = 0; w < 8; w++) {
            unsigned int word = 0;
            for (int k = 0; k < 32; k++) {
                int j = w * 32 + k;
                float bx1 = sb[j][0], by1 = sb[j][1], bx2 = sb[j][2], by2 = sb[j][3];
                float ba = (bx2 - bx1) * (by2 - by1);
                float lx = fmaxf(ax1, bx1), ly = fmaxf(ay1, by1);
                float rx = fminf(ax2, bx2), ry = fminf(ay2, by2);
                float ww = fmaxf(rx - lx, 0.0f), hh = fmaxf(ry - ly, 0.0f);
                float inter = ww * hh;
                float iou = inter / fmaxf(aa + ba - inter, 1e-9f);
                if (iou > NMS_TH) word |= (1u << k);
            }
            supmask[t][w] = word;
        }
    }
    __syncthreads();

    // serial greedy (bits only for j<i are set in keptw when row i is tested)
    if (t == 0) {
        for (int i = 0; i < NR; i++) {
            unsigned int sup = 0;
            // mask off bits >= i in the word containing i
            for (int w = 0; w < 8; w++) {
                unsigned int m = supmask[i][w] & keptw[w];
                if (w == (i >> 5)) m &= ((i & 31) ? ((1u << (i & 31)) - 1u) : 0u);
                else if (w > (i >> 5)) m = 0u;
                sup |= m;
            }
            if (!sup) keptw[i >> 5] |= (1u << (i & 31));
        }
    }
    __syncthreads();

    // keep for original index t (its sorted position is rk)
    bool kp = (keptw[rk >> 5] >> (rk & 31)) & 1u;
    kp = kp && (s_i > SCORE_TH);
    smask[t] = kp ? s_i : -INFINITY;
    __syncthreads();

    int rank2 = 0;
    float mi = smask[t];
    for (int j = 0; j < NR; j++) {
        float mj = smask[j];
        rank2 += (mj > mi) || (mj == mi && j < t);
    }
    kp = kp && (rank2 < MAX_DET);

    const float* bsrc = boxes + (size_t)(n * NR + t) * 4;
    float* drow = det + (size_t)(n * NR + t) * 6;
    drow[0] = bsrc[0]; drow[1] = bsrc[1];
    drow[2] = bsrc[2]; drow[3] = bsrc[3];
    drow[4] = s_i;
    drow[5] = kp ? 1.0f : 0.0f;
}

// ---------------------------------------------------------------------------
extern "C" void kernel_launch(void* const* d_in, const int* in_sizes, int n_in,
                              void* d_out, int out_size) {
    const float* features = (const float*)d_in[0];
    const float* proposals = (const float*)d_in[1];
    const float* gt_boxes = (const float*)d_in[2];
    // d_in[3] = gt_classes (unused by reference)
    const float* W_cls = (const float*)d_in[4];
    const float* b_cls = (const float*)d_in[5];
    const float* W_box = (const float*)d_in[6];
    const float* b_box = (const float*)d_in[7];

    float* out = (float*)d_out;
    float* det = out;                          // 2*256*6 = 3072
    float* out_idx = out + NIMG * NR * 6;      // 2*256   = 512
    float* out_lbl = out_idx + NIMG * NR;      // 2*256   = 512

    float* featvec; cudaGetSymbolAddress((void**)&featvec, g_featvec);
    float* boxes;   cudaGetSymbolAddress((void**)&boxes, g_boxes);
    float* scores;  cudaGetSymbolAddress((void**)&scores, g_scores);

    match_kernel<<<NIMG, NR>>>(gt_boxes, proposals, out_idx, out_lbl);
    roi_kernel<<<dim3(NR, NIMG), 256>>>(features, proposals, featvec);
    head_kernel<<<NIMG * NR, 128>>>(featvec, proposals, W_cls, b_cls, W_box,
                                    b_box, boxes, scores);
    nms_kernel<<<NIMG, NR>>>(boxes, scores, det);
}